// round 10
// baseline (speedup 1.0000x reference)
#include <cuda_runtime.h>
#include <cstdint>

#define FEAT 32
#define RES_H 512
#define RES_W 128
#define HW (RES_H * RES_W)
#define PLANE_ELEMS (FEAT * HW)
#define TIME_STEP_F 0.00390625f   /* 1/(2*128), exact in fp32 */
#define INV_BOUNDS_F 0.625f       /* fp32(1/fp32(1.6)) == 0.625 exactly (XLA folds /1.6 -> *0.625) */
#define NBINS 128
#define CAP 16384                 /* max points per ix bin; mean ~7.9K, 10-sigma safe */
#define TP_BLOCKS 768             /* 3 planes * (HW/256) transpose tiles */
#define COLS_BYTES (3 * RES_H * FEAT * 4)   /* 196608 B dynamic smem */

// Planes re-laid-out as [W][H][F]: the column for a fixed ix (time index) is
// 64 KB CONTIGUOUS -> gather kernel stages it into smem with sequential reads.
__device__ __align__(256) float g_tp[3][PLANE_ELEMS];
// Binned point records: iy0 | iy1<<9 | iy2<<18 | orig_idx<<27.
__device__ unsigned long long g_binned[NBINS * CAP];   // 16 MB
// Zero-initialized at module load; re-zeroed by gather_kernel every run.
__device__ int g_bin_count[NBINS];

// Packed f32 pair multiply — IEEE rn per element, bit-identical to __fmul_rn.
__device__ __forceinline__ unsigned long long mul2(unsigned long long a,
                                                   unsigned long long b) {
    unsigned long long r;
    asm("mul.rn.f32x2 %0, %1, %2;" : "=l"(r) : "l"(a), "l"(b));
    return r;
}

// Index math — XLA-folded forms, round half-to-even, clamp. No FMA contraction.
__device__ __forceinline__ int idx_w(float c) {
    float v = __fmul_rn(__fadd_rn(c, 1.0f), 63.5f);     // 0.5*(128-1) folded
    int k = (int)rintf(v);
    return min(max(k, 0), RES_W - 1);
}
__device__ __forceinline__ int idx_h(float c) {
    float v = __fmul_rn(__fadd_rn(c, 1.0f), 255.5f);    // 0.5*(512-1) folded
    int k = (int)rintf(v);
    return min(max(k, 0), RES_H - 1);
}

// ---------------------------------------------------------------------------
// Prep kernel: blocks [0,768) transpose planes [F,HW] -> [W][H][F];
// blocks [768,...) bin points by ix (independent work, runs concurrently).
// ---------------------------------------------------------------------------
__global__ void prep_kernel(const float* __restrict__ p0,
                            const float* __restrict__ p1,
                            const float* __restrict__ p2,
                            const float* __restrict__ pts,
                            const float* __restrict__ tim,
                            int n) {
    __shared__ float tile[256][33];
    const int b = blockIdx.x;
    const int tid = threadIdx.x;

    if (b < TP_BLOCKS) {
        // ---- Transpose tile: 256 consecutive hw (= 2 iy rows x 128 ix) ----
        const int plane = b >> 8;                 // 256 tiles per plane
        const int hw0 = (b & 255) * 256;
        const float* __restrict__ src = (plane == 0) ? p0 : ((plane == 1) ? p1 : p2);
        float* __restrict__ dst = g_tp[plane];

        #pragma unroll
        for (int k = 0; k < 8; k++) {
            const int lin = tid + 256 * k;        // 0..2047
            const int f  = lin >> 6;              // 0..31
            const int vc = lin & 63;              // float4 column within 256 hw
            const float4 v = *(const float4*)&src[f * HW + hw0 + vc * 4];
            tile[vc * 4 + 0][f] = v.x;
            tile[vc * 4 + 1][f] = v.y;
            tile[vc * 4 + 2][f] = v.z;
            tile[vc * 4 + 3][f] = v.w;
        }
        __syncthreads();
        #pragma unroll
        for (int k = 0; k < 8; k++) {
            const int lin = tid + 256 * k;
            const int r  = lin >> 3;              // hw row within tile
            const int fc = lin & 7;               // float4 chunk of features
            const int hw = hw0 + r;
            const int iy = hw >> 7;               // hw / 128
            const int ix = hw & 127;
            float4 w;
            w.x = tile[r][fc * 4 + 0];
            w.y = tile[r][fc * 4 + 1];
            w.z = tile[r][fc * 4 + 2];
            w.w = tile[r][fc * 4 + 3];
            *(float4*)&dst[(ix * RES_H + iy) * FEAT + fc * 4] = w;
        }
    } else {
        // ---- Bin one point per thread ----
        const int i = (b - TP_BLOCKS) * 256 + tid;
        if (i < n) {
            const float t  = __fadd_rn(__fmul_rn(tim[i], 2.0f), -1.0f);
            const float q0 = __fmul_rn(-pts[3 * i + 0], INV_BOUNDS_F);
            const float q1 = __fmul_rn(-pts[3 * i + 1], INV_BOUNDS_F);
            const float q2 = __fmul_rn(-pts[3 * i + 2], INV_BOUNDS_F);
            const int ix  = idx_w(t);
            const unsigned long long rec =
                (unsigned long long)idx_h(q0)
                | ((unsigned long long)idx_h(q1) << 9)
                | ((unsigned long long)idx_h(q2) << 18)
                | ((unsigned long long)(unsigned)i << 27);
            const int pos = atomicAdd(&g_bin_count[ix], 1);
            if (pos < CAP) g_binned[ix * CAP + pos] = rec;
        }
    }
}

// ---------------------------------------------------------------------------
// Gather kernel: block b < 128 handles bin ix=b. Stages 3 contiguous 64 KB
// plane columns into smem (LTS: 24.6 MB total vs 384 MB of L2 gathers), then
// per point: smem gather + product + 2 scattered full-line 128B stores.
// Block 128 = last-point fixup (main loop masks oi == n-1 -> disjoint).
// ---------------------------------------------------------------------------
__global__ void __launch_bounds__(512)
gather_kernel(const float* __restrict__ pts,
              const float* __restrict__ tim,
              float* __restrict__ out,
              int n) {
    extern __shared__ float cols[];                // [3][RES_H][FEAT]
    const int b = blockIdx.x;
    const int tid = threadIdx.x;
    const long long nb = (long long)n * FEAT;

    if (b == NBINS) {
        // ---- Last-point fixup (lane = feature) ----
        if (tid < 32) {
            const int i = n - 1;
            const float t  = __fadd_rn(__fmul_rn(tim[i], 2.0f), -1.0f);
            const float p0 = __fmul_rn(-pts[3 * i + 0], INV_BOUNDS_F);
            const float p1 = __fmul_rn(-pts[3 * i + 1], INV_BOUNDS_F);
            const float p2 = __fmul_rn(-pts[3 * i + 2], INV_BOUNDS_F);
            const int ix = idx_w(t);
            const float fo = __fmul_rn(__fmul_rn(
                __ldg(&g_tp[0][(ix * RES_H + idx_h(p0)) * FEAT + tid]),
                __ldg(&g_tp[1][(ix * RES_H + idx_h(p1)) * FEAT + tid])),
                __ldg(&g_tp[2][(ix * RES_H + idx_h(p2)) * FEAT + tid]));
            // data.at[-1].add(-TIME_STEP): all 4 coords of the last row shift.
            const float ts = __fadd_rn(t,  -TIME_STEP_F);
            const float q0 = __fadd_rn(p0, -TIME_STEP_F);
            const float q1 = __fadd_rn(p1, -TIME_STEP_F);
            const float q2 = __fadd_rn(p2, -TIME_STEP_F);
            const int ixs = idx_w(ts);
            const float fs = __fmul_rn(__fmul_rn(
                __ldg(&g_tp[0][(ixs * RES_H + idx_h(q0)) * FEAT + tid]),
                __ldg(&g_tp[1][(ixs * RES_H + idx_h(q1)) * FEAT + tid])),
                __ldg(&g_tp[2][(ixs * RES_H + idx_h(q2)) * FEAT + tid]));
            const bool cond = __fadd_rn(p0, TIME_STEP_F) > 1.0f;
            out[(long long)i * FEAT + tid]      = cond ? fs : fo;   // feature_A
            out[nb + (long long)i * FEAT + tid] = cond ? fo : fs;   // feature_B
        }
        return;
    }

    const int ix = b;
    __shared__ int s_count;
    if (tid == 0) {
        int c = g_bin_count[ix];
        g_bin_count[ix] = 0;          // reset for the next (deterministic) run
        s_count = (c < CAP) ? c : CAP;
    }

    // Stage the 3 plane columns: 3 x 64 KB contiguous reads.
    float4* cols4 = (float4*)cols;
    const int col_f4 = RES_H * FEAT / 4;              // 4096 float4 per plane
    #pragma unroll
    for (int it = 0; it < 24; it++) {
        const int lin = tid + 512 * it;               // 0..12287
        const int plane = lin / col_f4;
        const int rem = lin - plane * col_f4;
        cols4[plane * col_f4 + rem] =
            *(const float4*)&g_tp[plane][(size_t)ix * (RES_H * FEAT) + rem * 4];
    }
    __syncthreads();
    const int count = s_count;

    const int warp = tid >> 5;
    const int lane = tid & 31;
    const int g = lane >> 3;            // point within quad
    const int fe4 = lane & 7;           // float4 feature chunk
    const unsigned last = (unsigned)(n - 1);

    for (int base = warp * 4; base < count; base += 64) {
        const int p = base + g;
        unsigned long long rec = 0;
        if (p < count) rec = g_binned[ix * CAP + p];
        const int iy0 = (int)(rec & 511);
        const int iy1 = (int)((rec >> 9) & 511);
        const int iy2 = (int)((rec >> 18) & 511);
        const unsigned oi = (unsigned)(rec >> 27);

        float4 a = cols4[(0 * RES_H + iy0) * 8 + fe4];
        float4 bb = cols4[(1 * RES_H + iy1) * 8 + fe4];
        float4 cc = cols4[(2 * RES_H + iy2) * 8 + fe4];
        const ulonglong2 ua = *reinterpret_cast<ulonglong2*>(&a);
        const ulonglong2 ub = *reinterpret_cast<ulonglong2*>(&bb);
        const ulonglong2 uc = *reinterpret_cast<ulonglong2*>(&cc);
        ulonglong2 rr;
        rr.x = mul2(mul2(ua.x, ub.x), uc.x);
        rr.y = mul2(mul2(ua.y, ub.y), uc.y);
        const float4 r = *reinterpret_cast<float4*>(&rr);

        if (p < count && oi != last) {
            __stcs((float4*)&out[(long long)oi * FEAT + fe4 * 4], r);       // A
            __stcs((float4*)&out[nb + (long long)oi * FEAT + fe4 * 4], r);  // B
        }
    }
}

extern "C" void kernel_launch(void* const* d_in, const int* in_sizes, int n_in,
                              void* d_out, int out_size) {
    const float* pts    = (const float*)d_in[0];
    const float* tim    = (const float*)d_in[1];
    const float* plane0 = (const float*)d_in[2];
    const float* plane1 = (const float*)d_in[3];
    const float* plane2 = (const float*)d_in[4];
    float* out = (float*)d_out;

    const int n = in_sizes[0] / 3;   // pts is [N,3]

    // 1) Fused transpose (768 blocks) + binning (ceil(n/256) blocks).
    const int bin_blocks = (n + 255) / 256;
    prep_kernel<<<TP_BLOCKS + bin_blocks, 256>>>(plane0, plane1, plane2,
                                                 pts, tim, n);

    // 2) Per-ix gather with smem-staged plane columns + fixup block.
    cudaFuncSetAttribute(gather_kernel,
                         cudaFuncAttributeMaxDynamicSharedMemorySize,
                         COLS_BYTES);
    gather_kernel<<<NBINS + 1, 512, COLS_BYTES>>>(pts, tim, out, n);
}

// round 11
// speedup vs baseline: 2.3991x; 2.3991x over previous
#include <cuda_runtime.h>

#define FEAT 32
#define RES_H 512
#define RES_W 128
#define HW (RES_H * RES_W)
#define PLANE_ELEMS (FEAT * HW)
#define TIME_STEP_F 0.00390625f   /* 1/(2*128), exact in fp32 */
#define INV_BOUNDS_F 0.625f       /* fp32(1/fp32(1.6)) == 0.625 exactly (XLA folds /1.6 -> *0.625) */
#define NBINS 128
#define NSTRIPES 32               /* atomic stripes per bin: 4096 counters total */
#define SLOT 512                  /* record slots per stripe (mean ~244, 17 sigma) */
#define TP_BLOCKS 768             /* 3 planes * (HW/256) transpose tiles */
#define SUBS 4                    /* gather sub-blocks per bin */
#define SPS (NSTRIPES / SUBS)     /* stripes per sub-block = 8 */
#define COLS_FLOATS (3 * RES_H * FEAT)            /* 49152 floats = 192KB */
#define RECS_U64 (SPS * SLOT)                     /* 4096 recs = 32KB */
#define SMEM_BYTES (COLS_FLOATS * 4 + RECS_U64 * 8)  /* 229376 B */

// Planes re-laid-out as [W][H][F]: column for fixed ix is 64 KB contiguous.
__device__ __align__(256) float g_tp[3][PLANE_ELEMS];
// Records: iy0 | iy1<<9 | iy2<<18 | orig_idx<<27.
__device__ unsigned long long g_binned[NBINS * NSTRIPES * SLOT];   // 16 MB
// Zero at module load; gather resets its own stripes each run.
__device__ int g_scnt[NBINS * NSTRIPES];

// Packed f32 pair multiply — IEEE rn per element, bit-identical to __fmul_rn.
__device__ __forceinline__ unsigned long long mul2(unsigned long long a,
                                                   unsigned long long b) {
    unsigned long long r;
    asm("mul.rn.f32x2 %0, %1, %2;" : "=l"(r) : "l"(a), "l"(b));
    return r;
}

// Index math — XLA-folded forms, round half-to-even, clamp. No FMA contraction.
__device__ __forceinline__ int idx_w(float c) {
    float v = __fmul_rn(__fadd_rn(c, 1.0f), 63.5f);     // 0.5*(128-1) folded
    int k = (int)rintf(v);
    return min(max(k, 0), RES_W - 1);
}
__device__ __forceinline__ int idx_h(float c) {
    float v = __fmul_rn(__fadd_rn(c, 1.0f), 255.5f);    // 0.5*(512-1) folded
    int k = (int)rintf(v);
    return min(max(k, 0), RES_H - 1);
}

// ---------------------------------------------------------------------------
// Prep: blocks [0,768) transpose [F,HW] -> [W][H][F]; the rest bin points by
// ix with STRIPED counters (4096 atomic addresses -> negligible contention).
// ---------------------------------------------------------------------------
__global__ void prep_kernel(const float* __restrict__ p0,
                            const float* __restrict__ p1,
                            const float* __restrict__ p2,
                            const float* __restrict__ pts,
                            const float* __restrict__ tim,
                            int n) {
    __shared__ float tile[256][33];
    const int b = blockIdx.x;
    const int tid = threadIdx.x;

    if (b < TP_BLOCKS) {
        const int plane = b >> 8;                 // 256 tiles per plane
        const int hw0 = (b & 255) * 256;
        const float* __restrict__ src = (plane == 0) ? p0 : ((plane == 1) ? p1 : p2);
        float* __restrict__ dst = g_tp[plane];

        #pragma unroll
        for (int k = 0; k < 8; k++) {
            const int lin = tid + 256 * k;
            const int f  = lin >> 6;
            const int vc = lin & 63;
            const float4 v = *(const float4*)&src[f * HW + hw0 + vc * 4];
            tile[vc * 4 + 0][f] = v.x;
            tile[vc * 4 + 1][f] = v.y;
            tile[vc * 4 + 2][f] = v.z;
            tile[vc * 4 + 3][f] = v.w;
        }
        __syncthreads();
        #pragma unroll
        for (int k = 0; k < 8; k++) {
            const int lin = tid + 256 * k;
            const int r  = lin >> 3;
            const int fc = lin & 7;
            const int hw = hw0 + r;
            const int iy = hw >> 7;
            const int ix = hw & 127;
            float4 w;
            w.x = tile[r][fc * 4 + 0];
            w.y = tile[r][fc * 4 + 1];
            w.z = tile[r][fc * 4 + 2];
            w.w = tile[r][fc * 4 + 3];
            *(float4*)&dst[(ix * RES_H + iy) * FEAT + fc * 4] = w;
        }
    } else {
        const int i = (b - TP_BLOCKS) * 256 + tid;
        if (i < n) {
            const float t  = __fadd_rn(__fmul_rn(tim[i], 2.0f), -1.0f);
            const float q0 = __fmul_rn(-pts[3 * i + 0], INV_BOUNDS_F);
            const float q1 = __fmul_rn(-pts[3 * i + 1], INV_BOUNDS_F);
            const float q2 = __fmul_rn(-pts[3 * i + 2], INV_BOUNDS_F);
            const int ix = idx_w(t);
            const unsigned long long rec =
                (unsigned long long)idx_h(q0)
                | ((unsigned long long)idx_h(q1) << 9)
                | ((unsigned long long)idx_h(q2) << 18)
                | ((unsigned long long)(unsigned)i << 27);
            const int stripe = (b ^ (tid >> 5)) & (NSTRIPES - 1);
            const int slot_base = ix * NSTRIPES + stripe;
            const int pos = atomicAdd(&g_scnt[slot_base], 1);
            if (pos < SLOT) g_binned[(size_t)slot_base * SLOT + pos] = rec;
        }
    }
}

// ---------------------------------------------------------------------------
// Gather: block b < 512 handles bin b>>2, stripe group (b&3)*8..+8.
// Stages 3 x 64KB plane columns + its 32KB of records into smem, then the
// inner loop is pure LDS -> LDS.128 x3 -> mul -> 2x STG.128 (full lines).
// Block 512 = last-point fixup (main loops mask oi == n-1 -> disjoint).
// ---------------------------------------------------------------------------
__global__ void __launch_bounds__(1024)
gather_kernel(const float* __restrict__ pts,
              const float* __restrict__ tim,
              float* __restrict__ out,
              int n) {
    extern __shared__ float smem[];
    float4* cols4 = (float4*)smem;                                 // 12288 f4
    unsigned long long* srecs = (unsigned long long*)(smem + COLS_FLOATS);
    __shared__ int s_cnt[SPS];

    const int b = blockIdx.x;
    const int tid = threadIdx.x;
    const long long nb = (long long)n * FEAT;

    if (b == NBINS * SUBS) {
        // ---- Last-point fixup (lane = feature) ----
        if (tid < 32) {
            const int i = n - 1;
            const float t  = __fadd_rn(__fmul_rn(tim[i], 2.0f), -1.0f);
            const float p0 = __fmul_rn(-pts[3 * i + 0], INV_BOUNDS_F);
            const float p1 = __fmul_rn(-pts[3 * i + 1], INV_BOUNDS_F);
            const float p2 = __fmul_rn(-pts[3 * i + 2], INV_BOUNDS_F);
            const int ix = idx_w(t);
            const float fo = __fmul_rn(__fmul_rn(
                __ldg(&g_tp[0][(ix * RES_H + idx_h(p0)) * FEAT + tid]),
                __ldg(&g_tp[1][(ix * RES_H + idx_h(p1)) * FEAT + tid])),
                __ldg(&g_tp[2][(ix * RES_H + idx_h(p2)) * FEAT + tid]));
            // data.at[-1].add(-TIME_STEP): all 4 coords of the last row shift.
            const float ts = __fadd_rn(t,  -TIME_STEP_F);
            const float q0 = __fadd_rn(p0, -TIME_STEP_F);
            const float q1 = __fadd_rn(p1, -TIME_STEP_F);
            const float q2 = __fadd_rn(p2, -TIME_STEP_F);
            const int ixs = idx_w(ts);
            const float fs = __fmul_rn(__fmul_rn(
                __ldg(&g_tp[0][(ixs * RES_H + idx_h(q0)) * FEAT + tid]),
                __ldg(&g_tp[1][(ixs * RES_H + idx_h(q1)) * FEAT + tid])),
                __ldg(&g_tp[2][(ixs * RES_H + idx_h(q2)) * FEAT + tid]));
            const bool cond = __fadd_rn(p0, TIME_STEP_F) > 1.0f;
            out[(long long)i * FEAT + tid]      = cond ? fs : fo;   // feature_A
            out[nb + (long long)i * FEAT + tid] = cond ? fo : fs;   // feature_B
        }
        return;
    }

    const int bin = b >> 2;
    const int sub = b & 3;
    const int stripe0 = bin * NSTRIPES + sub * SPS;

    // Read + reset my 8 stripe counters.
    if (tid < SPS) {
        const int c = g_scnt[stripe0 + tid];
        g_scnt[stripe0 + tid] = 0;
        s_cnt[tid] = (c < SLOT) ? c : SLOT;
    }

    // Stage 3 plane columns (3 x 64KB contiguous).
    #pragma unroll
    for (int it = 0; it < 12; it++) {
        const int lin = tid + 1024 * it;              // 0..12287
        const int plane = lin >> 12;                  // /4096
        const int rem = lin & 4095;
        cols4[lin] = *(const float4*)&g_tp[plane][(size_t)bin * (RES_H * FEAT) + rem * 4];
    }
    // Stage my 32KB of records (stripes are consecutive -> contiguous region).
    const size_t rec_base = (size_t)stripe0 * SLOT;
    #pragma unroll
    for (int it = 0; it < 4; it++) {
        const int lin = tid + 1024 * it;              // 0..4095
        srecs[lin] = g_binned[rec_base + lin];
    }
    __syncthreads();

    const int wid = tid >> 5;
    const int lane = tid & 31;
    const int sl = wid >> 2;            // my stripe (0..7); 4 warps per stripe
    const int qp = wid & 3;             // quad phase within stripe
    const int g = lane >> 3;            // point within quad
    const int fe4 = lane & 7;           // float4 feature chunk
    const int cnt = s_cnt[sl];
    const unsigned last = (unsigned)(n - 1);

    for (int pb = qp * 4; pb < cnt; pb += 16) {
        const int p = pb + g;
        unsigned long long rec = 0;
        if (p < cnt) rec = srecs[sl * SLOT + p];
        const int iy0 = (int)(rec & 511);
        const int iy1 = (int)((rec >> 9) & 511);
        const int iy2 = (int)((rec >> 18) & 511);
        const unsigned oi = (unsigned)(rec >> 27);

        float4 a = cols4[(0 * RES_H + iy0) * 8 + fe4];
        float4 bb = cols4[(1 * RES_H + iy1) * 8 + fe4];
        float4 cc = cols4[(2 * RES_H + iy2) * 8 + fe4];
        const ulonglong2 ua = *reinterpret_cast<ulonglong2*>(&a);
        const ulonglong2 ub = *reinterpret_cast<ulonglong2*>(&bb);
        const ulonglong2 uc = *reinterpret_cast<ulonglong2*>(&cc);
        ulonglong2 rr;
        rr.x = mul2(mul2(ua.x, ub.x), uc.x);
        rr.y = mul2(mul2(ua.y, ub.y), uc.y);
        const float4 r = *reinterpret_cast<float4*>(&rr);

        if (p < cnt && oi != last) {
            __stcs((float4*)&out[(long long)oi * FEAT + fe4 * 4], r);       // A
            __stcs((float4*)&out[nb + (long long)oi * FEAT + fe4 * 4], r);  // B
        }
    }
}

extern "C" void kernel_launch(void* const* d_in, const int* in_sizes, int n_in,
                              void* d_out, int out_size) {
    const float* pts    = (const float*)d_in[0];
    const float* tim    = (const float*)d_in[1];
    const float* plane0 = (const float*)d_in[2];
    const float* plane1 = (const float*)d_in[3];
    const float* plane2 = (const float*)d_in[4];
    float* out = (float*)d_out;

    const int n = in_sizes[0] / 3;   // pts is [N,3]

    // 1) Fused transpose + striped binning.
    const int bin_blocks = (n + 255) / 256;
    prep_kernel<<<TP_BLOCKS + bin_blocks, 256>>>(plane0, plane1, plane2,
                                                 pts, tim, n);

    // 2) Per-(bin, stripe-group) gather with smem-staged columns + records.
    cudaFuncSetAttribute(gather_kernel,
                         cudaFuncAttributeMaxDynamicSharedMemorySize,
                         SMEM_BYTES);
    gather_kernel<<<NBINS * SUBS + 1, 1024, SMEM_BYTES>>>(pts, tim, out, n);
}

// round 12
// speedup vs baseline: 4.1368x; 1.7243x over previous
#include <cuda_runtime.h>

#define FEAT 32
#define RES_H 512
#define RES_W 128
#define HW (RES_H * RES_W)
#define PLANE_ELEMS (FEAT * HW)
#define TIME_STEP_F 0.00390625f   /* 1/(2*128), exact in fp32 */
#define INV_BOUNDS_F 0.625f       /* fp32(1/fp32(1.6)) == 0.625 exactly (XLA folds /1.6 -> *0.625) */
#define PPW 32                    /* points per warp */

// 3 transposed planes, layout [H][W][F]: 32 features contiguous (one 128B line).
__device__ __align__(256) float g_tp[3][PLANE_ELEMS];

// Packed f32 pair multiply (sm_103a) — IEEE rn per element, bit-identical to
// two scalar __fmul_rn.
__device__ __forceinline__ unsigned long long mul2(unsigned long long a,
                                                   unsigned long long b) {
    unsigned long long r;
    asm("mul.rn.f32x2 %0, %1, %2;" : "=l"(r) : "l"(a), "l"(b));
    return r;
}

// L2-only 16B gather (bypass L1: random access over 25 MB -> no L1 reuse).
__device__ __forceinline__ ulonglong2 ldcg2(const float* p) {
    ulonglong2 v;
    asm("ld.global.cg.v2.u64 {%0, %1}, [%2];"
        : "=l"(v.x), "=l"(v.y) : "l"(p));
    return v;
}

// ---------------------------------------------------------------------------
// Pre-pass: transpose [F=32, HW] -> [HW, F]. 256 hw x 32 f tiles, float4 both
// global sides, MLP=8. At its 50 MB DRAM floor (~8 us).
// ---------------------------------------------------------------------------
__global__ void transpose_planes(const float* __restrict__ p0,
                                 const float* __restrict__ p1,
                                 const float* __restrict__ p2) {
    __shared__ float tile[256][33];
    const int plane = blockIdx.y;
    const float* __restrict__ src = (plane == 0) ? p0 : ((plane == 1) ? p1 : p2);
    float* __restrict__ dst = g_tp[plane];

    const int hw0 = blockIdx.x * 256;
    const int tid = threadIdx.x;

    #pragma unroll
    for (int k = 0; k < 8; k++) {
        const int lin = tid + 256 * k;
        const int f  = lin >> 6;
        const int vc = lin & 63;
        const float4 v = *(const float4*)&src[f * HW + hw0 + vc * 4];
        tile[vc * 4 + 0][f] = v.x;
        tile[vc * 4 + 1][f] = v.y;
        tile[vc * 4 + 2][f] = v.z;
        tile[vc * 4 + 3][f] = v.w;
    }
    __syncthreads();
    #pragma unroll
    for (int k = 0; k < 8; k++) {
        const int lin = tid + 256 * k;
        const int r  = lin >> 3;
        const int fc = lin & 7;
        float4 w;
        w.x = tile[r][fc * 4 + 0];
        w.y = tile[r][fc * 4 + 1];
        w.z = tile[r][fc * 4 + 2];
        w.w = tile[r][fc * 4 + 3];
        *(float4*)&dst[(hw0 + r) * FEAT + fc * 4] = w;
    }
}

// ---------------------------------------------------------------------------
// Index math — XLA-folded forms, round half-to-even, clamp. No FMA contraction.
// ---------------------------------------------------------------------------
__device__ __forceinline__ int idx_w(float c) {
    float v = __fmul_rn(__fadd_rn(c, 1.0f), 63.5f);     // 0.5*(128-1) folded
    int k = (int)rintf(v);
    return min(max(k, 0), RES_W - 1);
}
__device__ __forceinline__ int idx_h(float c) {
    float v = __fmul_rn(__fadd_rn(c, 1.0f), 255.5f);    // 0.5*(512-1) folded
    int k = (int)rintf(v);
    return min(max(k, 0), RES_H - 1);
}

// ---------------------------------------------------------------------------
// Main kernel: warp handles PPW=32 points. LTS-capped at ~50 us:
// 656 MB L2 traffic (16 in + 384 gather + 256 store) at ~13 TB/s LTS ceiling.
// ---------------------------------------------------------------------------
__global__ void __launch_bounds__(256, 6)
displacement_kernel(const float* __restrict__ pts,
                    const float* __restrict__ tim,
                    float* __restrict__ out,
                    int n) {
    const int warp_id = blockIdx.x * (blockDim.x >> 5) + (threadIdx.x >> 5);
    const int lane = threadIdx.x & 31;
    const long long nb = (long long)n * FEAT;

    // ---- Fused last-point fixup (warp 0 only; writes rows for i = n-1) ----
    if (warp_id == 0) {
        const int i = n - 1;
        const float t  = __fadd_rn(__fmul_rn(tim[i], 2.0f), -1.0f);
        const float p0 = __fmul_rn(-pts[3 * i + 0], INV_BOUNDS_F);
        const float p1 = __fmul_rn(-pts[3 * i + 1], INV_BOUNDS_F);
        const float p2 = __fmul_rn(-pts[3 * i + 2], INV_BOUNDS_F);
        const int ix = idx_w(t);
        const float fo = __fmul_rn(__fmul_rn(
            __ldg(&g_tp[0][(idx_h(p0) * RES_W + ix) * FEAT + lane]),
            __ldg(&g_tp[1][(idx_h(p1) * RES_W + ix) * FEAT + lane])),
            __ldg(&g_tp[2][(idx_h(p2) * RES_W + ix) * FEAT + lane]));
        // data.at[-1].add(-TIME_STEP): all 4 coords of the last row shift.
        const float ts = __fadd_rn(t,  -TIME_STEP_F);
        const float q0 = __fadd_rn(p0, -TIME_STEP_F);
        const float q1 = __fadd_rn(p1, -TIME_STEP_F);
        const float q2 = __fadd_rn(p2, -TIME_STEP_F);
        const int ixs = idx_w(ts);
        const float fs = __fmul_rn(__fmul_rn(
            __ldg(&g_tp[0][(idx_h(q0) * RES_W + ixs) * FEAT + lane]),
            __ldg(&g_tp[1][(idx_h(q1) * RES_W + ixs) * FEAT + lane])),
            __ldg(&g_tp[2][(idx_h(q2) * RES_W + ixs) * FEAT + lane]));
        const bool cond = __fadd_rn(p0, TIME_STEP_F) > 1.0f;
        out[(long long)i * FEAT + lane]      = cond ? fs : fo;   // feature_A
        out[nb + (long long)i * FEAT + lane] = cond ? fo : fs;   // feature_B
    }

    const int base = warp_id * PPW;
    if (base >= n) return;

    // Phase 1: one point per lane.
    int b0 = 0, b1 = 0, b2 = 0;
    const int li = base + lane;
    if (li < n) {
        const float t  = __fadd_rn(__fmul_rn(tim[li], 2.0f), -1.0f);
        const float p0 = __fmul_rn(-pts[3 * li + 0], INV_BOUNDS_F);
        const float p1 = __fmul_rn(-pts[3 * li + 1], INV_BOUNDS_F);
        const float p2 = __fmul_rn(-pts[3 * li + 2], INV_BOUNDS_F);
        const int ix = idx_w(t);
        b0 = (idx_h(p0) * RES_W + ix) * FEAT;
        b1 = (idx_h(p1) * RES_W + ix) * FEAT;
        b2 = (idx_h(p2) * RES_W + ix) * FEAT;
    }

    const int g  = lane >> 3;          // point within quad
    const int fe = (lane & 7) * 4;     // feature chunk
    const int n_main = n - 1;          // point n-1 handled by fixup

    if (base + PPW <= n_main) {
        // ---- Fast path: unguarded quads ----
        #pragma unroll
        for (int j = 0; j < PPW / 4; j++) {
            const int src = j * 4 + g;
            const int i = base + src;
            const int o0 = __shfl_sync(0xffffffffu, b0, src) + fe;
            const int o1 = __shfl_sync(0xffffffffu, b1, src) + fe;
            const int o2 = __shfl_sync(0xffffffffu, b2, src) + fe;
            const ulonglong2 a = ldcg2(&g_tp[0][o0]);
            const ulonglong2 b = ldcg2(&g_tp[1][o1]);
            const ulonglong2 c = ldcg2(&g_tp[2][o2]);
            ulonglong2 rr;
            rr.x = mul2(mul2(a.x, b.x), c.x);
            rr.y = mul2(mul2(a.y, b.y), c.y);
            const float4 r = *(float4*)&rr;
            __stcs((float4*)&out[(long long)i * FEAT + fe], r);        // A
            __stcs((float4*)&out[nb + (long long)i * FEAT + fe], r);   // B
        }
    } else {
        // ---- Tail path: guarded per quad ----
        #pragma unroll
        for (int j = 0; j < PPW / 4; j++) {
            const int src = j * 4 + g;
            const int i = base + src;
            const int o0 = __shfl_sync(0xffffffffu, b0, src) + fe;
            const int o1 = __shfl_sync(0xffffffffu, b1, src) + fe;
            const int o2 = __shfl_sync(0xffffffffu, b2, src) + fe;
            if (i < n_main) {
                const ulonglong2 a = ldcg2(&g_tp[0][o0]);
                const ulonglong2 b = ldcg2(&g_tp[1][o1]);
                const ulonglong2 c = ldcg2(&g_tp[2][o2]);
                ulonglong2 rr;
                rr.x = mul2(mul2(a.x, b.x), c.x);
                rr.y = mul2(mul2(a.y, b.y), c.y);
                const float4 r = *(float4*)&rr;
                __stcs((float4*)&out[(long long)i * FEAT + fe], r);
                __stcs((float4*)&out[nb + (long long)i * FEAT + fe], r);
            }
        }
    }
}

extern "C" void kernel_launch(void* const* d_in, const int* in_sizes, int n_in,
                              void* d_out, int out_size) {
    const float* pts    = (const float*)d_in[0];
    const float* tim    = (const float*)d_in[1];
    const float* plane0 = (const float*)d_in[2];
    const float* plane1 = (const float*)d_in[3];
    const float* plane2 = (const float*)d_in[4];
    float* out = (float*)d_out;

    const int n = in_sizes[0] / 3;   // pts is [N,3]

    // 1) Transpose planes into [H,W,F] scratch.
    dim3 tg(HW / 256, 3);
    transpose_planes<<<tg, 256>>>(plane0, plane1, plane2);

    // 2) Main gather-product-store (fixup fused): 32 points per warp.
    const int block = 256;                         // 8 warps
    const int pts_per_block = (block / 32) * PPW;  // 256
    const int grid = (n + pts_per_block - 1) / pts_per_block;
    displacement_kernel<<<grid, block>>>(pts, tim, out, n);
}

// round 13
// speedup vs baseline: 4.2302x; 1.0226x over previous
#include <cuda_runtime.h>

#define FEAT 32
#define RES_H 512
#define RES_W 128
#define HW (RES_H * RES_W)
#define PLANE_ELEMS (FEAT * HW)
#define TIME_STEP_F 0.00390625f   /* 1/(2*128), exact in fp32 */
#define INV_BOUNDS_F 0.625f       /* fp32(1/fp32(1.6)) == 0.625 exactly (XLA folds /1.6 -> *0.625) */
#define PPW 32                    /* points per warp */

// 3 transposed planes, layout [H][W][F]: 32 features contiguous (one 128B line).
__device__ __align__(256) float g_tp[3][PLANE_ELEMS];

// Packed f32 pair multiply (sm_103a) — IEEE rn per element, bit-identical to
// two scalar __fmul_rn.
__device__ __forceinline__ unsigned long long mul2(unsigned long long a,
                                                   unsigned long long b) {
    unsigned long long r;
    asm("mul.rn.f32x2 %0, %1, %2;" : "=l"(r) : "l"(a), "l"(b));
    return r;
}

// L2-only 16B gather (bypass L1: random access over 25 MB -> no L1 reuse).
__device__ __forceinline__ ulonglong2 ldcg2(const float* p) {
    ulonglong2 v;
    asm("ld.global.cg.v2.u64 {%0, %1}, [%2];"
        : "=l"(v.x), "=l"(v.y) : "l"(p));
    return v;
}

// ---------------------------------------------------------------------------
// Pre-pass: transpose [F=32, HW] -> [HW, F]. 256 hw x 32 f tiles, float4 both
// global sides, MLP=8. Source read with streaming hint (read-once data;
// preserve L2 capacity for the transposed planes the main kernel gathers).
// ---------------------------------------------------------------------------
__global__ void transpose_planes(const float* __restrict__ p0,
                                 const float* __restrict__ p1,
                                 const float* __restrict__ p2) {
    __shared__ float tile[256][33];
    const int plane = blockIdx.y;
    const float* __restrict__ src = (plane == 0) ? p0 : ((plane == 1) ? p1 : p2);
    float* __restrict__ dst = g_tp[plane];

    const int hw0 = blockIdx.x * 256;
    const int tid = threadIdx.x;

    #pragma unroll
    for (int k = 0; k < 8; k++) {
        const int lin = tid + 256 * k;
        const int f  = lin >> 6;
        const int vc = lin & 63;
        const float4 v = __ldcs((const float4*)&src[f * HW + hw0 + vc * 4]);
        tile[vc * 4 + 0][f] = v.x;
        tile[vc * 4 + 1][f] = v.y;
        tile[vc * 4 + 2][f] = v.z;
        tile[vc * 4 + 3][f] = v.w;
    }
    __syncthreads();
    #pragma unroll
    for (int k = 0; k < 8; k++) {
        const int lin = tid + 256 * k;
        const int r  = lin >> 3;
        const int fc = lin & 7;
        float4 w;
        w.x = tile[r][fc * 4 + 0];
        w.y = tile[r][fc * 4 + 1];
        w.z = tile[r][fc * 4 + 2];
        w.w = tile[r][fc * 4 + 3];
        *(float4*)&dst[(hw0 + r) * FEAT + fc * 4] = w;
    }
}

// ---------------------------------------------------------------------------
// Index math — XLA-folded forms, round half-to-even, clamp. No FMA contraction.
// ---------------------------------------------------------------------------
__device__ __forceinline__ int idx_w(float c) {
    float v = __fmul_rn(__fadd_rn(c, 1.0f), 63.5f);     // 0.5*(128-1) folded
    int k = (int)rintf(v);
    return min(max(k, 0), RES_W - 1);
}
__device__ __forceinline__ int idx_h(float c) {
    float v = __fmul_rn(__fadd_rn(c, 1.0f), 255.5f);    // 0.5*(512-1) folded
    int k = (int)rintf(v);
    return min(max(k, 0), RES_H - 1);
}

// ---------------------------------------------------------------------------
// Main kernel: warp handles PPW=32 points. At the LTS roofline (~51 us):
// 656 MB L2 traffic (16 in + 384 gather + 256 store) at the ~12.8 TB/s
// path-independent LTS ceiling. All gather bytes are useful (32 feats = one
// 128B line per plane per point); no further traffic reduction exists at
// fp32 precision.
// ---------------------------------------------------------------------------
__global__ void __launch_bounds__(256, 6)
displacement_kernel(const float* __restrict__ pts,
                    const float* __restrict__ tim,
                    float* __restrict__ out,
                    int n) {
    const int warp_id = blockIdx.x * (blockDim.x >> 5) + (threadIdx.x >> 5);
    const int lane = threadIdx.x & 31;
    const long long nb = (long long)n * FEAT;

    // ---- Fused last-point fixup (warp 0 only; writes rows for i = n-1) ----
    if (warp_id == 0) {
        const int i = n - 1;
        const float t  = __fadd_rn(__fmul_rn(tim[i], 2.0f), -1.0f);
        const float p0 = __fmul_rn(-pts[3 * i + 0], INV_BOUNDS_F);
        const float p1 = __fmul_rn(-pts[3 * i + 1], INV_BOUNDS_F);
        const float p2 = __fmul_rn(-pts[3 * i + 2], INV_BOUNDS_F);
        const int ix = idx_w(t);
        const float fo = __fmul_rn(__fmul_rn(
            __ldg(&g_tp[0][(idx_h(p0) * RES_W + ix) * FEAT + lane]),
            __ldg(&g_tp[1][(idx_h(p1) * RES_W + ix) * FEAT + lane])),
            __ldg(&g_tp[2][(idx_h(p2) * RES_W + ix) * FEAT + lane]));
        // data.at[-1].add(-TIME_STEP): all 4 coords of the last row shift.
        const float ts = __fadd_rn(t,  -TIME_STEP_F);
        const float q0 = __fadd_rn(p0, -TIME_STEP_F);
        const float q1 = __fadd_rn(p1, -TIME_STEP_F);
        const float q2 = __fadd_rn(p2, -TIME_STEP_F);
        const int ixs = idx_w(ts);
        const float fs = __fmul_rn(__fmul_rn(
            __ldg(&g_tp[0][(idx_h(q0) * RES_W + ixs) * FEAT + lane]),
            __ldg(&g_tp[1][(idx_h(q1) * RES_W + ixs) * FEAT + lane])),
            __ldg(&g_tp[2][(idx_h(q2) * RES_W + ixs) * FEAT + lane]));
        const bool cond = __fadd_rn(p0, TIME_STEP_F) > 1.0f;
        out[(long long)i * FEAT + lane]      = cond ? fs : fo;   // feature_A
        out[nb + (long long)i * FEAT + lane] = cond ? fo : fs;   // feature_B
    }

    const int base = warp_id * PPW;
    if (base >= n) return;

    // Phase 1: one point per lane.
    int b0 = 0, b1 = 0, b2 = 0;
    const int li = base + lane;
    if (li < n) {
        const float t  = __fadd_rn(__fmul_rn(tim[li], 2.0f), -1.0f);
        const float p0 = __fmul_rn(-pts[3 * li + 0], INV_BOUNDS_F);
        const float p1 = __fmul_rn(-pts[3 * li + 1], INV_BOUNDS_F);
        const float p2 = __fmul_rn(-pts[3 * li + 2], INV_BOUNDS_F);
        const int ix = idx_w(t);
        b0 = (idx_h(p0) * RES_W + ix) * FEAT;
        b1 = (idx_h(p1) * RES_W + ix) * FEAT;
        b2 = (idx_h(p2) * RES_W + ix) * FEAT;
    }

    const int g  = lane >> 3;          // point within quad
    const int fe = (lane & 7) * 4;     // feature chunk
    const int n_main = n - 1;          // point n-1 handled by fixup

    if (base + PPW <= n_main) {
        // ---- Fast path: unguarded quads ----
        #pragma unroll
        for (int j = 0; j < PPW / 4; j++) {
            const int src = j * 4 + g;
            const int i = base + src;
            const int o0 = __shfl_sync(0xffffffffu, b0, src) + fe;
            const int o1 = __shfl_sync(0xffffffffu, b1, src) + fe;
            const int o2 = __shfl_sync(0xffffffffu, b2, src) + fe;
            const ulonglong2 a = ldcg2(&g_tp[0][o0]);
            const ulonglong2 b = ldcg2(&g_tp[1][o1]);
            const ulonglong2 c = ldcg2(&g_tp[2][o2]);
            ulonglong2 rr;
            rr.x = mul2(mul2(a.x, b.x), c.x);
            rr.y = mul2(mul2(a.y, b.y), c.y);
            const float4 r = *(float4*)&rr;
            __stcs((float4*)&out[(long long)i * FEAT + fe], r);        // A
            __stcs((float4*)&out[nb + (long long)i * FEAT + fe], r);   // B
        }
    } else {
        // ---- Tail path: guarded per quad ----
        #pragma unroll
        for (int j = 0; j < PPW / 4; j++) {
            const int src = j * 4 + g;
            const int i = base + src;
            const int o0 = __shfl_sync(0xffffffffu, b0, src) + fe;
            const int o1 = __shfl_sync(0xffffffffu, b1, src) + fe;
            const int o2 = __shfl_sync(0xffffffffu, b2, src) + fe;
            if (i < n_main) {
                const ulonglong2 a = ldcg2(&g_tp[0][o0]);
                const ulonglong2 b = ldcg2(&g_tp[1][o1]);
                const ulonglong2 c = ldcg2(&g_tp[2][o2]);
                ulonglong2 rr;
                rr.x = mul2(mul2(a.x, b.x), c.x);
                rr.y = mul2(mul2(a.y, b.y), c.y);
                const float4 r = *(float4*)&rr;
                __stcs((float4*)&out[(long long)i * FEAT + fe], r);
                __stcs((float4*)&out[nb + (long long)i * FEAT + fe], r);
            }
        }
    }
}

extern "C" void kernel_launch(void* const* d_in, const int* in_sizes, int n_in,
                              void* d_out, int out_size) {
    const float* pts    = (const float*)d_in[0];
    const float* tim    = (const float*)d_in[1];
    const float* plane0 = (const float*)d_in[2];
    const float* plane1 = (const float*)d_in[3];
    const float* plane2 = (const float*)d_in[4];
    float* out = (float*)d_out;

    const int n = in_sizes[0] / 3;   // pts is [N,3]

    // 1) Transpose planes into [H,W,F] scratch.
    dim3 tg(HW / 256, 3);
    transpose_planes<<<tg, 256>>>(plane0, plane1, plane2);

    // 2) Main gather-product-store (fixup fused): 32 points per warp.
    const int block = 256;                         // 8 warps
    const int pts_per_block = (block / 32) * PPW;  // 256
    const int grid = (n + pts_per_block - 1) / pts_per_block;
    displacement_kernel<<<grid, block>>>(pts, tim, out, n);
}

// round 14
// speedup vs baseline: 4.2512x; 1.0050x over previous
#include <cuda_runtime.h>

#define FEAT 32
#define RES_H 512
#define RES_W 128
#define HW (RES_H * RES_W)
#define PLANE_ELEMS (FEAT * HW)
#define TIME_STEP_F 0.00390625f   /* 1/(2*128), exact in fp32 */
#define INV_BOUNDS_F 0.625f       /* fp32(1/fp32(1.6)) == 0.625 exactly (XLA folds /1.6 -> *0.625) */
#define PPW 32                    /* points per warp */

// 3 transposed planes, layout [H][W][F]: 32 features contiguous (one 128B line).
__device__ __align__(256) float g_tp[3][PLANE_ELEMS];

// Packed f32 pair multiply (sm_103a) — IEEE rn per element, bit-identical to
// two scalar __fmul_rn.
__device__ __forceinline__ unsigned long long mul2(unsigned long long a,
                                                   unsigned long long b) {
    unsigned long long r;
    asm("mul.rn.f32x2 %0, %1, %2;" : "=l"(r) : "l"(a), "l"(b));
    return r;
}

// L2-only 16B gather (bypass L1: random access over 25 MB -> no L1 reuse).
__device__ __forceinline__ ulonglong2 ldcg2(const float* p) {
    ulonglong2 v;
    asm("ld.global.cg.v2.u64 {%0, %1}, [%2];"
        : "=l"(v.x), "=l"(v.y) : "l"(p));
    return v;
}

// ---------------------------------------------------------------------------
// Pre-pass: transpose [F=32, HW] -> [HW, F]. 256 hw x 32 f tiles, float4 both
// global sides, MLP=8. Source read with streaming hint (read-once data;
// preserve L2 capacity for the transposed planes the main kernel gathers).
// At its 50 MB DRAM floor (~7.5 us).
// ---------------------------------------------------------------------------
__global__ void transpose_planes(const float* __restrict__ p0,
                                 const float* __restrict__ p1,
                                 const float* __restrict__ p2) {
    __shared__ float tile[256][33];
    const int plane = blockIdx.y;
    const float* __restrict__ src = (plane == 0) ? p0 : ((plane == 1) ? p1 : p2);
    float* __restrict__ dst = g_tp[plane];

    const int hw0 = blockIdx.x * 256;
    const int tid = threadIdx.x;

    #pragma unroll
    for (int k = 0; k < 8; k++) {
        const int lin = tid + 256 * k;
        const int f  = lin >> 6;
        const int vc = lin & 63;
        const float4 v = __ldcs((const float4*)&src[f * HW + hw0 + vc * 4]);
        tile[vc * 4 + 0][f] = v.x;
        tile[vc * 4 + 1][f] = v.y;
        tile[vc * 4 + 2][f] = v.z;
        tile[vc * 4 + 3][f] = v.w;
    }
    __syncthreads();
    #pragma unroll
    for (int k = 0; k < 8; k++) {
        const int lin = tid + 256 * k;
        const int r  = lin >> 3;
        const int fc = lin & 7;
        float4 w;
        w.x = tile[r][fc * 4 + 0];
        w.y = tile[r][fc * 4 + 1];
        w.z = tile[r][fc * 4 + 2];
        w.w = tile[r][fc * 4 + 3];
        *(float4*)&dst[(hw0 + r) * FEAT + fc * 4] = w;
    }
}

// ---------------------------------------------------------------------------
// Index math — XLA-folded forms, round half-to-even, clamp. No FMA contraction.
// ---------------------------------------------------------------------------
__device__ __forceinline__ int idx_w(float c) {
    float v = __fmul_rn(__fadd_rn(c, 1.0f), 63.5f);     // 0.5*(128-1) folded
    int k = (int)rintf(v);
    return min(max(k, 0), RES_W - 1);
}
__device__ __forceinline__ int idx_h(float c) {
    float v = __fmul_rn(__fadd_rn(c, 1.0f), 255.5f);    // 0.5*(512-1) folded
    int k = (int)rintf(v);
    return min(max(k, 0), RES_H - 1);
}

// ---------------------------------------------------------------------------
// Main kernel: warp handles PPW=32 points. At the LTS roofline (~51 us):
// 656 MB L2 traffic (16 in + 384 gather + 256 store) at the ~12.6-12.9 TB/s
// path-independent LTS ceiling. All gather bytes are useful (32 feats = one
// 128B line per plane per point); no further traffic reduction exists at
// fp32 precision.
// ---------------------------------------------------------------------------
__global__ void __launch_bounds__(256, 6)
displacement_kernel(const float* __restrict__ pts,
                    const float* __restrict__ tim,
                    float* __restrict__ out,
                    int n) {
    const int warp_id = blockIdx.x * (blockDim.x >> 5) + (threadIdx.x >> 5);
    const int lane = threadIdx.x & 31;
    const long long nb = (long long)n * FEAT;

    // ---- Fused last-point fixup (warp 0 only; writes rows for i = n-1) ----
    if (warp_id == 0) {
        const int i = n - 1;
        const float t  = __fadd_rn(__fmul_rn(tim[i], 2.0f), -1.0f);
        const float p0 = __fmul_rn(-pts[3 * i + 0], INV_BOUNDS_F);
        const float p1 = __fmul_rn(-pts[3 * i + 1], INV_BOUNDS_F);
        const float p2 = __fmul_rn(-pts[3 * i + 2], INV_BOUNDS_F);
        const int ix = idx_w(t);
        const float fo = __fmul_rn(__fmul_rn(
            __ldg(&g_tp[0][(idx_h(p0) * RES_W + ix) * FEAT + lane]),
            __ldg(&g_tp[1][(idx_h(p1) * RES_W + ix) * FEAT + lane])),
            __ldg(&g_tp[2][(idx_h(p2) * RES_W + ix) * FEAT + lane]));
        // data.at[-1].add(-TIME_STEP): all 4 coords of the last row shift.
        const float ts = __fadd_rn(t,  -TIME_STEP_F);
        const float q0 = __fadd_rn(p0, -TIME_STEP_F);
        const float q1 = __fadd_rn(p1, -TIME_STEP_F);
        const float q2 = __fadd_rn(p2, -TIME_STEP_F);
        const int ixs = idx_w(ts);
        const float fs = __fmul_rn(__fmul_rn(
            __ldg(&g_tp[0][(idx_h(q0) * RES_W + ixs) * FEAT + lane]),
            __ldg(&g_tp[1][(idx_h(q1) * RES_W + ixs) * FEAT + lane])),
            __ldg(&g_tp[2][(idx_h(q2) * RES_W + ixs) * FEAT + lane]));
        const bool cond = __fadd_rn(p0, TIME_STEP_F) > 1.0f;
        out[(long long)i * FEAT + lane]      = cond ? fs : fo;   // feature_A
        out[nb + (long long)i * FEAT + lane] = cond ? fo : fs;   // feature_B
    }

    const int base = warp_id * PPW;
    if (base >= n) return;

    // Phase 1: one point per lane.
    int b0 = 0, b1 = 0, b2 = 0;
    const int li = base + lane;
    if (li < n) {
        const float t  = __fadd_rn(__fmul_rn(tim[li], 2.0f), -1.0f);
        const float p0 = __fmul_rn(-pts[3 * li + 0], INV_BOUNDS_F);
        const float p1 = __fmul_rn(-pts[3 * li + 1], INV_BOUNDS_F);
        const float p2 = __fmul_rn(-pts[3 * li + 2], INV_BOUNDS_F);
        const int ix = idx_w(t);
        b0 = (idx_h(p0) * RES_W + ix) * FEAT;
        b1 = (idx_h(p1) * RES_W + ix) * FEAT;
        b2 = (idx_h(p2) * RES_W + ix) * FEAT;
    }

    const int g  = lane >> 3;          // point within quad
    const int fe = (lane & 7) * 4;     // feature chunk
    const int n_main = n - 1;          // point n-1 handled by fixup

    if (base + PPW <= n_main) {
        // ---- Fast path: unguarded quads ----
        #pragma unroll
        for (int j = 0; j < PPW / 4; j++) {
            const int src = j * 4 + g;
            const int i = base + src;
            const int o0 = __shfl_sync(0xffffffffu, b0, src) + fe;
            const int o1 = __shfl_sync(0xffffffffu, b1, src) + fe;
            const int o2 = __shfl_sync(0xffffffffu, b2, src) + fe;
            const ulonglong2 a = ldcg2(&g_tp[0][o0]);
            const ulonglong2 b = ldcg2(&g_tp[1][o1]);
            const ulonglong2 c = ldcg2(&g_tp[2][o2]);
            ulonglong2 rr;
            rr.x = mul2(mul2(a.x, b.x), c.x);
            rr.y = mul2(mul2(a.y, b.y), c.y);
            const float4 r = *(float4*)&rr;
            __stcs((float4*)&out[(long long)i * FEAT + fe], r);        // A
            __stcs((float4*)&out[nb + (long long)i * FEAT + fe], r);   // B
        }
    } else {
        // ---- Tail path: guarded per quad ----
        #pragma unroll
        for (int j = 0; j < PPW / 4; j++) {
            const int src = j * 4 + g;
            const int i = base + src;
            const int o0 = __shfl_sync(0xffffffffu, b0, src) + fe;
            const int o1 = __shfl_sync(0xffffffffu, b1, src) + fe;
            const int o2 = __shfl_sync(0xffffffffu, b2, src) + fe;
            if (i < n_main) {
                const ulonglong2 a = ldcg2(&g_tp[0][o0]);
                const ulonglong2 b = ldcg2(&g_tp[1][o1]);
                const ulonglong2 c = ldcg2(&g_tp[2][o2]);
                ulonglong2 rr;
                rr.x = mul2(mul2(a.x, b.x), c.x);
                rr.y = mul2(mul2(a.y, b.y), c.y);
                const float4 r = *(float4*)&rr;
                __stcs((float4*)&out[(long long)i * FEAT + fe], r);
                __stcs((float4*)&out[nb + (long long)i * FEAT + fe], r);
            }
        }
    }
}

extern "C" void kernel_launch(void* const* d_in, const int* in_sizes, int n_in,
                              void* d_out, int out_size) {
    const float* pts    = (const float*)d_in[0];
    const float* tim    = (const float*)d_in[1];
    const float* plane0 = (const float*)d_in[2];
    const float* plane1 = (const float*)d_in[3];
    const float* plane2 = (const float*)d_in[4];
    float* out = (float*)d_out;

    const int n = in_sizes[0] / 3;   // pts is [N,3]

    // 1) Transpose planes into [H,W,F] scratch.
    dim3 tg(HW / 256, 3);
    transpose_planes<<<tg, 256>>>(plane0, plane1, plane2);

    // 2) Main gather-product-store (fixup fused): 32 points per warp.
    const int block = 256;                         // 8 warps
    const int pts_per_block = (block / 32) * PPW;  // 256
    const int grid = (n + pts_per_block - 1) / pts_per_block;
    displacement_kernel<<<grid, block>>>(pts, tim, out, n);
}